// round 3
// baseline (speedup 1.0000x reference)
#include <cuda_runtime.h>

#define B_ 32
#define D_ 256
#define T_ 2048
#define K_ 1024
#define N_ (B_ * T_)            // 65536 vectors
#define QSIZE (B_ * D_ * T_)    // 16777216 quantized elements

#define BN 128   // t-vectors per block (argmin kernel)
#define TK 64    // codes per k-tile
#define DC 16    // d per smem chunk

// Scratch (no device allocation allowed -> __device__ globals)
__device__ float  g_e2[K_];
__device__ float  g_x2[N_];
__device__ int    g_idx[N_];
__device__ double g_loss;

// ---------------------------------------------------------------------------
// Kernel 1: e2[k] = fl32(sum_d fl32(E[k,d]^2)), and zero the loss accumulator.
// Double accumulation of fp32 squares -> correctly rounded; ref's pairwise
// fp32 sum differs by <=1 ulp of ~8e-5, negligible vs the 1.5e-5 rounding
// granularity of the big-x2 add downstream.
// ---------------------------------------------------------------------------
__global__ void e2_kernel(const float* __restrict__ E) {
    int k = blockIdx.x;
    int d = threadIdx.x;
    float v = E[(size_t)k * D_ + d];
    float sq = __fmul_rn(v, v);          // fp32 square, like ref's flat**2
    __shared__ double s[256];
    s[d] = (double)sq;
    __syncthreads();
    for (int off = 128; off > 0; off >>= 1) {
        if (d < off) s[d] += s[d + off];
        __syncthreads();
    }
    if (d == 0) g_e2[k] = (float)s[0];
    if (k == 0 && d == 0) g_loss = 0.0;
}

// ---------------------------------------------------------------------------
// Kernel 1b: x2[n] = fl32(sum_d fl32(X[b,d,t]^2)) per vector (b,t).
// Any few-ulp difference vs ref's sum order is a uniform shift of the whole
// distance row (round-to-nearest is translation-invariant by ulp multiples
// within a binade) and cancels in argmin.
// ---------------------------------------------------------------------------
__global__ __launch_bounds__(256) void x2_kernel(const float* __restrict__ X) {
    int b = blockIdx.y;
    int t = blockIdx.x * 256 + threadIdx.x;
    const float* xp = X + (size_t)b * (D_ * T_) + t;
    double acc = 0.0;
#pragma unroll 8
    for (int d = 0; d < D_; d++) {
        float x = xp[(size_t)d * T_];
        float sq = __fmul_rn(x, x);
        acc += (double)sq;
    }
    g_x2[b * T_ + t] = (float)acc;
}

// ---------------------------------------------------------------------------
// Kernel 2: fused distance-GEMM + argmin, with reference-exact fp32 rounding
// in the epilogue:  d_k = fl32( fl32(x2 + e2[k]) - 2*fl32(dot) ).
// Block: 128 t-vectors (one batch b), 16 k-tiles of 64 codes.
// 256 threads: tx = tid&31 -> 4 consecutive t; ty = tid>>5 -> 8 consecutive
// codes. 4n x 8k fp32 accumulators per thread.
// Tie-break: strict <, equal -> smaller k (argmin first occurrence).
// ---------------------------------------------------------------------------
__global__ __launch_bounds__(256) void argmin_kernel(
    const float* __restrict__ X, const float* __restrict__ E)
{
    __shared__ __align__(16) float Xs[DC][BN];   // [d][t_local]
    __shared__ __align__(16) float Es[DC][TK];   // [d][k_local]
    __shared__ float rbest[BN][8];
    __shared__ int   ridx[BN][8];

    const int b   = blockIdx.y;
    const int t0  = blockIdx.x * BN;
    const int tid = threadIdx.x;
    const int tx  = tid & 31;
    const int ty  = tid >> 5;

    const float* Xb = X + (size_t)b * (D_ * T_) + t0;

    float x2r[4];
#pragma unroll
    for (int i = 0; i < 4; i++) x2r[i] = g_x2[b * T_ + t0 + tx * 4 + i];

    float best[4];
    int   bidx[4];
#pragma unroll
    for (int i = 0; i < 4; i++) { best[i] = 3.4e38f; bidx[i] = 0; }

    for (int k0 = 0; k0 < K_; k0 += TK) {
        float acc[4][8];
#pragma unroll
        for (int i = 0; i < 4; i++)
#pragma unroll
            for (int j = 0; j < 8; j++) acc[i][j] = 0.f;

        for (int d0 = 0; d0 < D_; d0 += DC) {
            // Stage X tile: DC x BN = 2048 floats = 512 float4, 2 per thread.
#pragma unroll
            for (int i = 0; i < 2; i++) {
                int e4 = tid + i * 256;      // 0..511
                int r  = e4 >> 5;            // d within chunk
                int c4 = e4 & 31;            // float4 within row
                float4 v = *reinterpret_cast<const float4*>(
                    Xb + (size_t)(d0 + r) * T_ + c4 * 4);
                *reinterpret_cast<float4*>(&Xs[r][c4 * 4]) = v;
            }
            // Stage E tile transposed: TK x DC = 1024 floats, 4 per thread.
#pragma unroll
            for (int i = 0; i < 4; i++) {
                int e  = tid + i * 256;      // 0..1023
                int k  = e >> 4;             // 0..63
                int dd = e & 15;             // 0..15
                Es[dd][k] = E[(size_t)(k0 + k) * D_ + d0 + dd];
            }
            __syncthreads();

#pragma unroll
            for (int dd = 0; dd < DC; dd++) {
                float xr[4], er[8];
#pragma unroll
                for (int i = 0; i < 4; i++) xr[i] = Xs[dd][tx * 4 + i];
#pragma unroll
                for (int j = 0; j < 8; j++) er[j] = Es[dd][ty * 8 + j];
#pragma unroll
                for (int i = 0; i < 4; i++)
#pragma unroll
                    for (int j = 0; j < 8; j++)
                        acc[i][j] = fmaf(xr[i], er[j], acc[i][j]);
            }
            __syncthreads();
        }

        // Epilogue: emulate ref's fp32 rounding exactly. No FMA contraction.
#pragma unroll
        for (int j = 0; j < 8; j++) {
            int k = k0 + ty * 8 + j;
            float e2 = g_e2[k];
#pragma unroll
            for (int i = 0; i < 4; i++) {
                float C    = __fadd_rn(x2r[i], e2);              // x2 + e2
                float m2g  = __fmul_rn(-2.0f, acc[i][j]);        // exact
                float dist = __fadd_rn(C, m2g);                  // fl(C - 2G)
                if (dist < best[i]) { best[i] = dist; bidx[i] = k; }
            }
        }
    }

    // Reduce across the 8 ty-threads sharing each t (lexicographic on (v,k)).
#pragma unroll
    for (int i = 0; i < 4; i++) {
        rbest[tx * 4 + i][ty] = best[i];
        ridx [tx * 4 + i][ty] = bidx[i];
    }
    __syncthreads();
    if (ty == 0) {
#pragma unroll
        for (int i = 0; i < 4; i++) {
            int nl = tx * 4 + i;
            float bv = rbest[nl][0];
            int   bi = ridx [nl][0];
#pragma unroll
            for (int j = 1; j < 8; j++) {
                float v  = rbest[nl][j];
                int   id = ridx [nl][j];
                if (v < bv || (v == bv && id < bi)) { bv = v; bi = id; }
            }
            g_idx[(size_t)b * T_ + t0 + nl] = bi;
        }
    }
}

// ---------------------------------------------------------------------------
// Kernel 3: gather codebook rows -> quantized output [B, D, T] layout,
// fused loss partial sums (q and e latent losses are numerically equal).
// ---------------------------------------------------------------------------
__global__ __launch_bounds__(256) void gather_kernel(
    const float* __restrict__ X, const float* __restrict__ E,
    float* __restrict__ out)
{
    int b = blockIdx.y;
    int t = blockIdx.x * 256 + threadIdx.x;
    int n = b * T_ + t;
    int idx = g_idx[n];

    const float* erow = E + (size_t)idx * D_;
    const float* xp   = X   + (size_t)b * (D_ * T_) + t;
    float*       op   = out + (size_t)b * (D_ * T_) + t;

    float sum = 0.f;
#pragma unroll 8
    for (int d = 0; d < D_; d++) {
        float e = __ldg(erow + d);
        float x = xp[(size_t)d * T_];
        op[(size_t)d * T_] = e;
        float df = e - x;
        sum = fmaf(df, df, sum);
    }

    __shared__ float s[256];
    s[threadIdx.x] = sum;
    __syncthreads();
    for (int off = 128; off > 0; off >>= 1) {
        if (threadIdx.x < off) s[threadIdx.x] += s[threadIdx.x + off];
        __syncthreads();
    }
    if (threadIdx.x == 0) atomicAdd(&g_loss, (double)s[0]);
}

// ---------------------------------------------------------------------------
// Kernel 4: write loss scalar and indices (as float) after quantized.
// loss = q_latent + 0.25 * e_latent = 1.25 * mean((q - x)^2)
// ---------------------------------------------------------------------------
__global__ void finalize_kernel(float* __restrict__ out, int out_size) {
    int i = blockIdx.x * blockDim.x + threadIdx.x;
    if (i == 0 && out_size > QSIZE) {
        out[QSIZE] = (float)(g_loss * 1.25 / (double)QSIZE);
    }
    if (i < N_ && out_size >= QSIZE + 1 + N_) {
        out[QSIZE + 1 + i] = (float)g_idx[i];
    }
}

// ---------------------------------------------------------------------------
extern "C" void kernel_launch(void* const* d_in, const int* in_sizes, int n_in,
                              void* d_out, int out_size) {
    const float* X = (const float*)d_in[0];   // [B, D, T] f32
    const float* E = (const float*)d_in[1];   // [K, D]   f32
    float* out = (float*)d_out;

    e2_kernel<<<K_, 256>>>(E);
    x2_kernel<<<dim3(T_ / 256, B_), 256>>>(X);
    argmin_kernel<<<dim3(T_ / BN, B_), 256>>>(X, E);
    gather_kernel<<<dim3(T_ / 256, B_), 256>>>(X, E, out);
    finalize_kernel<<<(N_ + 255) / 256, 256>>>(out, out_size);
}

// round 6
// speedup vs baseline: 1.0791x; 1.0791x over previous
#include <cuda_runtime.h>

#define B_ 32
#define D_ 256
#define T_ 2048
#define K_ 1024
#define N_ (B_ * T_)            // 65536 vectors
#define QSIZE (B_ * D_ * T_)    // 16777216 quantized elements

#define BN 128   // t-vectors per block (argmin kernel)
#define TK 64    // codes per k-tile
#define DC 16    // d per smem chunk

// Scratch (no device allocation allowed -> __device__ globals)
__device__ float  g_e2[K_];
__device__ float  g_x2[N_];
__device__ int    g_idx[N_];
__device__ double g_loss;

typedef unsigned long long u64;

// Packed fp32x2 FMA (Blackwell FFMA2). Each 32-bit half is an independent
// fp32 FMA -> per-output accumulation order identical to scalar FFMA code.
__device__ __forceinline__ void ffma2(u64& acc, u64 a, u64 b) {
    asm("fma.rn.f32x2 %0, %1, %2, %0;" : "+l"(acc) : "l"(a), "l"(b));
}
__device__ __forceinline__ u64 pack2(float lo, float hi) {
    u64 r;
    asm("mov.b64 %0, {%1, %2};" : "=l"(r) : "f"(lo), "f"(hi));
    return r;
}
__device__ __forceinline__ void unpack2(u64 v, float& lo, float& hi) {
    asm("mov.b64 {%0, %1}, %2;" : "=f"(lo), "=f"(hi) : "l"(v));
}

// ---------------------------------------------------------------------------
// Kernel 1: e2[k] = fl32(sum_d fl32(E[k,d]^2)), and zero the loss accumulator.
// ---------------------------------------------------------------------------
__global__ void e2_kernel(const float* __restrict__ E) {
    int k = blockIdx.x;
    int d = threadIdx.x;
    float v = E[(size_t)k * D_ + d];
    float sq = __fmul_rn(v, v);
    __shared__ double s[256];
    s[d] = (double)sq;
    __syncthreads();
    for (int off = 128; off > 0; off >>= 1) {
        if (d < off) s[d] += s[d + off];
        __syncthreads();
    }
    if (d == 0) g_e2[k] = (float)s[0];
    if (k == 0 && d == 0) g_loss = 0.0;
}

// ---------------------------------------------------------------------------
// Kernel 1b: x2[n] = fl32(sum_d fl32(X[b,d,t]^2)) per vector (b,t).
// ---------------------------------------------------------------------------
__global__ __launch_bounds__(256) void x2_kernel(const float* __restrict__ X) {
    int b = blockIdx.y;
    int t = blockIdx.x * 256 + threadIdx.x;
    const float* xp = X + (size_t)b * (D_ * T_) + t;
    double acc = 0.0;
#pragma unroll 8
    for (int d = 0; d < D_; d++) {
        float x = xp[(size_t)d * T_];
        float sq = __fmul_rn(x, x);
        acc += (double)sq;
    }
    g_x2[b * T_ + t] = (float)acc;
}

// ---------------------------------------------------------------------------
// Kernel 2: fused distance-GEMM + argmin, FFMA2 (fp32x2) mainloop.
// Block: 128 t-vectors (one batch b), 16 k-tiles of 64 codes.
// 256 threads: tx = tid&31 -> 4 consecutive t; ty = tid>>5 -> 8 consecutive
// codes. 4n x 8k fp32 accumulators, packed in pairs along k -> 4n x 4 u64.
// Epilogue emulates ref's fp32 rounding: d = fl(fl(x2+e2) - 2*fl(dot)).
// Tie-break: strict <, equal -> smaller k (argmin first occurrence).
// ---------------------------------------------------------------------------
__global__ __launch_bounds__(256) void argmin_kernel(
    const float* __restrict__ X, const float* __restrict__ E)
{
    __shared__ __align__(16) float Xs[DC][BN];   // [d][t_local]
    __shared__ __align__(16) float Es[DC][TK];   // [d][k_local]
    __shared__ float rbest[BN][8];
    __shared__ int   ridx[BN][8];

    const int b   = blockIdx.y;
    const int t0  = blockIdx.x * BN;
    const int tid = threadIdx.x;
    const int tx  = tid & 31;
    const int ty  = tid >> 5;

    const float* Xb = X + (size_t)b * (D_ * T_) + t0;

    float x2r[4];
#pragma unroll
    for (int i = 0; i < 4; i++) x2r[i] = g_x2[b * T_ + t0 + tx * 4 + i];

    float best[4];
    int   bidx[4];
#pragma unroll
    for (int i = 0; i < 4; i++) { best[i] = 3.4e38f; bidx[i] = 0; }

    for (int k0 = 0; k0 < K_; k0 += TK) {
        u64 acc2[4][4];   // [t][k-pair]; halves = codes 2j (lo), 2j+1 (hi)
#pragma unroll
        for (int i = 0; i < 4; i++)
#pragma unroll
            for (int j = 0; j < 4; j++) acc2[i][j] = 0ull;

        for (int d0 = 0; d0 < D_; d0 += DC) {
            // Stage X tile: DC x BN = 2048 floats = 512 float4, 2 per thread.
#pragma unroll
            for (int i = 0; i < 2; i++) {
                int e4 = tid + i * 256;      // 0..511
                int r  = e4 >> 5;            // d within chunk
                int c4 = e4 & 31;            // float4 within row
                float4 v = *reinterpret_cast<const float4*>(
                    Xb + (size_t)(d0 + r) * T_ + c4 * 4);
                *reinterpret_cast<float4*>(&Xs[r][c4 * 4]) = v;
            }
            // Stage E tile transposed: TK x DC = 1024 floats, 4 per thread.
#pragma unroll
            for (int i = 0; i < 4; i++) {
                int e  = tid + i * 256;      // 0..1023
                int k  = e >> 4;             // 0..63
                int dd = e & 15;             // 0..15
                Es[dd][k] = E[(size_t)(k0 + k) * D_ + d0 + dd];
            }
            __syncthreads();

#pragma unroll
            for (int dd = 0; dd < DC; dd++) {
                float4 xv = *reinterpret_cast<const float4*>(&Xs[dd][tx * 4]);
                float xr[4] = {xv.x, xv.y, xv.z, xv.w};
                u64 er2[4];
#pragma unroll
                for (int j = 0; j < 4; j++)
                    er2[j] = *reinterpret_cast<const u64*>(
                        &Es[dd][ty * 8 + 2 * j]);
#pragma unroll
                for (int i = 0; i < 4; i++) {
                    u64 xp2 = pack2(xr[i], xr[i]);
#pragma unroll
                    for (int j = 0; j < 4; j++)
                        ffma2(acc2[i][j], xp2, er2[j]);
                }
            }
            __syncthreads();
        }

        // Epilogue: emulate ref's fp32 rounding exactly. No FMA contraction.
#pragma unroll
        for (int j = 0; j < 4; j++) {
            int klo = k0 + ty * 8 + 2 * j;
            float e2lo = g_e2[klo];
            float e2hi = g_e2[klo + 1];
#pragma unroll
            for (int i = 0; i < 4; i++) {
                float glo, ghi;
                unpack2(acc2[i][j], glo, ghi);
                float Clo = __fadd_rn(x2r[i], e2lo);
                float dlo = __fadd_rn(Clo, __fmul_rn(-2.0f, glo));
                if (dlo < best[i]) { best[i] = dlo; bidx[i] = klo; }
                float Chi = __fadd_rn(x2r[i], e2hi);
                float dhi = __fadd_rn(Chi, __fmul_rn(-2.0f, ghi));
                if (dhi < best[i]) { best[i] = dhi; bidx[i] = klo + 1; }
            }
        }
    }

    // Reduce across the 8 ty-threads sharing each t (lexicographic on (v,k)).
#pragma unroll
    for (int i = 0; i < 4; i++) {
        rbest[tx * 4 + i][ty] = best[i];
        ridx [tx * 4 + i][ty] = bidx[i];
    }
    __syncthreads();
    if (ty == 0) {
#pragma unroll
        for (int i = 0; i < 4; i++) {
            int nl = tx * 4 + i;
            float bv = rbest[nl][0];
            int   bi = ridx [nl][0];
#pragma unroll
            for (int j = 1; j < 8; j++) {
                float v  = rbest[nl][j];
                int   id = ridx [nl][j];
                if (v < bv || (v == bv && id < bi)) { bv = v; bi = id; }
            }
            g_idx[(size_t)b * T_ + t0 + nl] = bi;
        }
    }
}

// ---------------------------------------------------------------------------
// Kernel 3: gather codebook rows -> quantized output, smem-staged so both
// codebook reads (coalesced 128B row chunks) and output writes (coalesced
// over t) are clean. Fused loss partial sums.
// Block: 256 t's of one batch; loops 8 chunks of 32 d.
// ---------------------------------------------------------------------------
__global__ __launch_bounds__(256) void gather_kernel(
    const float* __restrict__ X, const float* __restrict__ E,
    float* __restrict__ out)
{
    __shared__ float sq[256][33];   // stride 33 -> conflict-free both phases
    __shared__ int   sidx[256];

    const int b   = blockIdx.y;
    const int t0  = blockIdx.x * 256;
    const int tid = threadIdx.x;
    const int t   = t0 + tid;

    sidx[tid] = g_idx[b * T_ + t];
    __syncthreads();

    const int rg = tid >> 3;    // row group 0..31
    const int rl = tid & 7;     // float4 within 32-float chunk

    float loss = 0.f;
    for (int d0 = 0; d0 < D_; d0 += 32) {
        // Stage: 32 rows per pass, 8 threads/row load 128B coalesced.
#pragma unroll
        for (int r0 = 0; r0 < 256; r0 += 32) {
            int row = r0 + rg;
            float4 v = *reinterpret_cast<const float4*>(
                E + (size_t)sidx[row] * D_ + d0 + rl * 4);
            sq[row][rl * 4 + 0] = v.x;
            sq[row][rl * 4 + 1] = v.y;
            sq[row][rl * 4 + 2] = v.z;
            sq[row][rl * 4 + 3] = v.w;
        }
        __syncthreads();
        // Emit: thread owns t, writes 32 d's coalesced across the warp.
#pragma unroll
        for (int dd = 0; dd < 32; dd++) {
            int d = d0 + dd;
            float e = sq[tid][dd];
            float x = X[((size_t)b * D_ + d) * T_ + t];
            out[((size_t)b * D_ + d) * T_ + t] = e;
            float df = e - x;
            loss = fmaf(df, df, loss);
        }
        __syncthreads();
    }

    // Block-reduce loss (reuse sq storage).
    float* s = &sq[0][0];
    s[tid] = loss;
    __syncthreads();
    for (int off = 128; off > 0; off >>= 1) {
        if (tid < off) s[tid] += s[tid + off];
        __syncthreads();
    }
    if (tid == 0) atomicAdd(&g_loss, (double)s[0]);
}

// ---------------------------------------------------------------------------
// Kernel 4: write loss scalar and indices (as float) after quantized.
// loss = q_latent + 0.25 * e_latent = 1.25 * mean((q - x)^2)
// ---------------------------------------------------------------------------
__global__ void finalize_kernel(float* __restrict__ out, int out_size) {
    int i = blockIdx.x * blockDim.x + threadIdx.x;
    if (i == 0 && out_size > QSIZE) {
        out[QSIZE] = (float)(g_loss * 1.25 / (double)QSIZE);
    }
    if (i < N_ && out_size >= QSIZE + 1 + N_) {
        out[QSIZE + 1 + i] = (float)g_idx[i];
    }
}

// ---------------------------------------------------------------------------
extern "C" void kernel_launch(void* const* d_in, const int* in_sizes, int n_in,
                              void* d_out, int out_size) {
    const float* X = (const float*)d_in[0];   // [B, D, T] f32
    const float* E = (const float*)d_in[1];   // [K, D]   f32
    float* out = (float*)d_out;

    e2_kernel<<<K_, 256>>>(E);
    x2_kernel<<<dim3(T_ / 256, B_), 256>>>(X);
    argmin_kernel<<<dim3(T_ / BN, B_), 256>>>(X, E);
    gather_kernel<<<dim3(T_ / 256, B_), 256>>>(X, E, out);
    finalize_kernel<<<(N_ + 255) / 256, 256>>>(out, out_size);
}

// round 8
// speedup vs baseline: 2.6402x; 2.4467x over previous
#include <cuda_runtime.h>
#include <cuda_fp16.h>
#include <cstdint>

#define B_ 32
#define D_ 256
#define T_ 2048
#define K_ 1024
#define N_ (B_ * T_)            // 65536 vectors
#define QSIZE (B_ * D_ * T_)    // 16777216 quantized elements

// ---------------- device scratch (no allocation allowed) -------------------
__device__ float  g_e2[K_];
__device__ float  g_x2[N_];
__device__ int    g_idx[N_];
__device__ double g_loss;
// Pre-split codebook (scaled by 2^14): e*2^14 = h + l exactly-enough (<=2^-24)
__device__ __align__(16) __half g_eh[K_ * D_];
__device__ __align__(16) __half g_el[K_ * D_];

#define SCALE_X 16.0f            // 2^4
#define SCALE_E 16384.0f         // 2^14
#define UNSCALE_M2 (-7.62939453125e-6f)   // -2 * 2^-18, exact power of two

// ---------------- smem layout (dynamic) -------------------------------------
// A: [split 0..1][kc 0..3] 16KB tiles of [128 tok][64 d fp16, SW128 rows]
#define SMA   0
#define SMB   131072   // B: [split][kc] 8KB tiles of [64 code][64 d fp16]
#define SME2  196608   // 64 floats
#define SMRV  196864   // 128*2 floats
#define SMRI  197888   // 128*2 ints
#define SMTOT 198912

__device__ __forceinline__ uint32_t smem_u32(const void* p) {
    uint32_t a;
    asm("{ .reg .u64 t; cvta.to.shared.u64 t, %1; cvt.u32.u64 %0, t; }"
        : "=r"(a) : "l"(p));
    return a;
}
__device__ __forceinline__ void ldsm_x4(uint32_t addr, uint32_t* r) {
    asm volatile(
        "ldmatrix.sync.aligned.m8n8.x4.shared.b16 {%0,%1,%2,%3}, [%4];"
        : "=r"(r[0]), "=r"(r[1]), "=r"(r[2]), "=r"(r[3]) : "r"(addr));
}
__device__ __forceinline__ void mma16816(float* c, const uint32_t* a,
                                         const uint32_t* b) {
    asm volatile(
        "mma.sync.aligned.m16n8k16.row.col.f32.f16.f16.f32 "
        "{%0,%1,%2,%3}, {%4,%5,%6,%7}, {%8,%9}, {%0,%1,%2,%3};"
        : "+f"(c[0]), "+f"(c[1]), "+f"(c[2]), "+f"(c[3])
        : "r"(a[0]), "r"(a[1]), "r"(a[2]), "r"(a[3]), "r"(b[0]), "r"(b[1]));
}

// ---------------------------------------------------------------------------
// Kernel 1: e2[k] = fl32(sum fl32(E^2)); zero loss accumulator.
// ---------------------------------------------------------------------------
__global__ void e2_kernel(const float* __restrict__ E) {
    int k = blockIdx.x;
    int d = threadIdx.x;
    float v = E[(size_t)k * D_ + d];
    float sq = __fmul_rn(v, v);
    __shared__ double s[256];
    s[d] = (double)sq;
    __syncthreads();
    for (int off = 128; off > 0; off >>= 1) {
        if (d < off) s[d] += s[d + off];
        __syncthreads();
    }
    if (d == 0) g_e2[k] = (float)s[0];
    if (k == 0 && d == 0) g_loss = 0.0;
}

// ---------------------------------------------------------------------------
// Kernel 1b: pre-split codebook into fp16 hi/lo of e*2^14.
// ---------------------------------------------------------------------------
__global__ void splitE_kernel(const float* __restrict__ E) {
    int k = blockIdx.x;
    int d = threadIdx.x;
    size_t o = (size_t)k * D_ + d;
    float es = __fmul_rn(E[o], SCALE_E);        // exact power-of-2 scale
    __half h = __float2half_rn(es);
    __half l = __float2half_rn(__fsub_rn(es, __half2float(h)));
    g_eh[o] = h;
    g_el[o] = l;
}

// ---------------------------------------------------------------------------
// Kernel 1c: x2[n] per vector.
// ---------------------------------------------------------------------------
__global__ __launch_bounds__(256) void x2_kernel(const float* __restrict__ X) {
    int b = blockIdx.y;
    int t = blockIdx.x * 256 + threadIdx.x;
    const float* xp = X + (size_t)b * (D_ * T_) + t;
    double acc = 0.0;
#pragma unroll 8
    for (int d = 0; d < D_; d++) {
        float x = xp[(size_t)d * T_];
        acc += (double)__fmul_rn(x, x);
    }
    g_x2[b * T_ + t] = (float)acc;
}

// ---------------------------------------------------------------------------
// Kernel 2: mma.sync (HMMA) distance GEMM + argmin.
// CTA = 128 tokens, 8 warps: wm = wid&3 (32-token group), wn = wid>>2
// (32-code half of the current 64-code tile). Warp tile 32x32, K=256 in 16
// k16-steps. dot = (AhBh + AhBl + AlBh) with fp16 splits of scaled x,e.
// Epilogue: dist = fl(fl(x2+e2) - 2*fl(dot)); strict <, tie -> smaller k.
// ---------------------------------------------------------------------------
__global__ __launch_bounds__(256, 1)
void argmin_mma_kernel(const float* __restrict__ X) {
    extern __shared__ char smem[];
    const uint32_t sb = smem_u32(smem);
    const int tid  = threadIdx.x;
    const int lane = tid & 31, wid = tid >> 5;
    const int wm = wid & 3, wn = wid >> 2;
    const int bx = blockIdx.x;
    const int b  = bx >> 4, t0 = (bx & 15) * 128;
    const int n0 = b * T_ + t0;
    const float* Xb = X + (size_t)b * (D_ * T_) + t0;

    // ---- stage A: X tile -> fp16 h/l (scaled by 2^4), SW128 [tok][d] ------
#pragma unroll 4
    for (int i = 0; i < 16; i++) {
        int idx = tid + i * 256;          // 0..4095
        int kc  = idx >> 10;              // 0..3
        int rem = idx & 1023;
        int dp  = rem >> 5;               // d-pair 0..31
        int c4  = rem & 31;               // float4 over tok
        int dg  = kc * 64 + dp * 2;
        float4 va = *(const float4*)(Xb + (size_t)dg * T_ + c4 * 4);
        float4 vb = *(const float4*)(Xb + (size_t)(dg + 1) * T_ + c4 * 4);
        float fa[4] = {va.x, va.y, va.z, va.w};
        float fb[4] = {vb.x, vb.y, vb.z, vb.w};
#pragma unroll
        for (int u = 0; u < 4; u++) {
            int tok = c4 * 4 + u;
            float x0 = __fmul_rn(fa[u], SCALE_X);
            float x1 = __fmul_rn(fb[u], SCALE_X);
            __half h0 = __float2half_rn(x0);
            __half l0 = __float2half_rn(__fsub_rn(x0, __half2float(h0)));
            __half h1 = __float2half_rn(x1);
            __half l1 = __float2half_rn(__fsub_rn(x1, __half2float(h1)));
            uint32_t off = (uint32_t)(tok * 128 + ((dp * 4) ^ ((tok & 7) << 4)));
            *(uint32_t*)(smem + SMA + kc * 16384 + off) =
                (uint32_t)__half_as_ushort(h0) |
                ((uint32_t)__half_as_ushort(h1) << 16);
            *(uint32_t*)(smem + SMA + 65536 + kc * 16384 + off) =
                (uint32_t)__half_as_ushort(l0) |
                ((uint32_t)__half_as_ushort(l1) << 16);
        }
    }

    // per-thread owned token rows (4 slots: mb*2 + rowhalf)
    float x2own[4];
#pragma unroll
    for (int slot = 0; slot < 4; slot++) {
        int trow = wm * 32 + (slot >> 1) * 16 + (slot & 1) * 8 + (lane >> 2);
        x2own[slot] = g_x2[n0 + trow];
    }

    float best[4];
    int   bidx[4];
#pragma unroll
    for (int s = 0; s < 4; s++) { best[s] = 3.4e38f; bidx[s] = 0; }

    // lane constants for ldmatrix addressing
    const int g = lane >> 3, r = lane & 7;
    const int tok0  = wm * 32 + (g & 1) * 8 + r;   // A row (mb adds 16)
    const int khA   = g >> 1;
    const uint32_t xrA = (uint32_t)((tok0 & 7) << 4);
    const int code0 = (g >> 1) * 8 + r;            // B row within 16-block
    const int khB   = g & 1;
    const uint32_t xrB = (uint32_t)((code0 & 7) << 4);

    for (int ct = 0; ct < 16; ct++) {
        int cbase = ct * 64;
        // ---- stage B tile: 64 codes x 256 d, both splits -----------------
#pragma unroll 4
        for (int i = 0; i < 16; i++) {
            int idx = tid + i * 256;       // 0..4095
            int s   = idx >> 11;
            int rem = idx & 2047;
            int kc  = rem >> 9;
            int r2  = rem & 511;
            int row = r2 >> 3, c16 = r2 & 7;
            const __half* src = (s ? g_el : g_eh)
                + (size_t)(cbase + row) * D_ + kc * 64 + c16 * 8;
            uint4 v = *(const uint4*)src;
            *(uint4*)(smem + SMB + s * 32768 + kc * 8192 + row * 128
                      + ((c16 * 16) ^ ((row & 7) << 4))) = v;
        }
        if (tid < 64) ((float*)(smem + SME2))[tid] = g_e2[cbase + tid];
        __syncthreads();

        // ---- mainloop: K = 256 in 16 k16 steps ---------------------------
        float acc[2][4][4];
#pragma unroll
        for (int mb = 0; mb < 2; mb++)
#pragma unroll
            for (int nb = 0; nb < 4; nb++)
#pragma unroll
                for (int e = 0; e < 4; e++) acc[mb][nb][e] = 0.f;

        for (int kc = 0; kc < 4; kc++) {
            uint32_t abase = sb + SMA + kc * 16384 + tok0 * 128;
            uint32_t bbase = sb + SMB + kc * 8192 + (wn * 32 + code0) * 128;
#pragma unroll
            for (int ks = 0; ks < 4; ks++) {
                uint32_t da = (uint32_t)((ks * 32 + khA * 16) ^ xrA);
                uint32_t db = (uint32_t)((ks * 32 + khB * 16) ^ xrB);
                uint32_t Ah[2][4], Al[2][4], Bh[2][4], Bl[2][4];
#pragma unroll
                for (int mb = 0; mb < 2; mb++) {
                    ldsm_x4(abase + mb * 2048 + da, Ah[mb]);
                    ldsm_x4(abase + 65536 + mb * 2048 + da, Al[mb]);
                }
#pragma unroll
                for (int n2 = 0; n2 < 2; n2++) {
                    ldsm_x4(bbase + n2 * 2048 + db, Bh[n2]);
                    ldsm_x4(bbase + 32768 + n2 * 2048 + db, Bl[n2]);
                }
#pragma unroll
                for (int mb = 0; mb < 2; mb++)
#pragma unroll
                    for (int nb = 0; nb < 4; nb++) {
                        const uint32_t* bh = &Bh[nb >> 1][2 * (nb & 1)];
                        const uint32_t* bl = &Bl[nb >> 1][2 * (nb & 1)];
                        mma16816(acc[mb][nb], Ah[mb], bh);
                        mma16816(acc[mb][nb], Ah[mb], bl);
                        mma16816(acc[mb][nb], Al[mb], bh);
                    }
            }
        }

        // ---- epilogue: exact ref rounding + running argmin ---------------
        const float* se2 = (const float*)(smem + SME2);
#pragma unroll
        for (int mb = 0; mb < 2; mb++)
#pragma unroll
            for (int nb = 0; nb < 4; nb++)
#pragma unroll
                for (int e = 0; e < 4; e++) {
                    int slot = mb * 2 + (e >> 1);
                    int col  = nb * 8 + 2 * (lane & 3) + (e & 1);
                    int k    = cbase + wn * 32 + col;
                    float C    = __fadd_rn(x2own[slot], se2[wn * 32 + col]);
                    float m2g  = __fmul_rn(acc[mb][nb][e], UNSCALE_M2); // exact
                    float dist = __fadd_rn(C, m2g);
                    if (dist < best[slot]) { best[slot] = dist; bidx[slot] = k; }
                }
        __syncthreads();
    }

    // ---- reduce: 4 lanes per row (shfl), then 2 wn warps (smem) ----------
    float* rv = (float*)(smem + SMRV);
    int*   ri = (int*)(smem + SMRI);
#pragma unroll
    for (int slot = 0; slot < 4; slot++) {
        float v = best[slot];
        int   ix = bidx[slot];
#pragma unroll
        for (int off = 1; off < 4; off <<= 1) {
            float ov = __shfl_xor_sync(0xffffffffu, v, off);
            int   oi = __shfl_xor_sync(0xffffffffu, ix, off);
            if (ov < v || (ov == v && oi < ix)) { v = ov; ix = oi; }
        }
        if ((lane & 3) == 0) {
            int trow = wm * 32 + (slot >> 1) * 16 + (slot & 1) * 8 + (lane >> 2);
            rv[trow * 2 + wn] = v;
            ri[trow * 2 + wn] = ix;
        }
    }
    __syncthreads();
    if (tid < 128) {
        float v0 = rv[tid * 2], v1 = rv[tid * 2 + 1];
        int   i0 = ri[tid * 2], i1 = ri[tid * 2 + 1];
        int sel = (v1 < v0 || (v1 == v0 && i1 < i0)) ? i1 : i0;
        g_idx[n0 + tid] = sel;
    }
}

// ---------------------------------------------------------------------------
// Kernel 3: gather codebook rows -> quantized output, fused loss.
// ---------------------------------------------------------------------------
__global__ __launch_bounds__(256) void gather_kernel(
    const float* __restrict__ X, const float* __restrict__ E,
    float* __restrict__ out)
{
    __shared__ float sq[256][33];
    __shared__ int   sidx[256];

    const int b   = blockIdx.y;
    const int t0  = blockIdx.x * 256;
    const int tid = threadIdx.x;
    const int t   = t0 + tid;

    sidx[tid] = g_idx[b * T_ + t];
    __syncthreads();

    const int rg = tid >> 3;
    const int rl = tid & 7;

    float loss = 0.f;
    for (int d0 = 0; d0 < D_; d0 += 32) {
#pragma unroll
        for (int r0 = 0; r0 < 256; r0 += 32) {
            int row = r0 + rg;
            float4 v = *reinterpret_cast<const float4*>(
                E + (size_t)sidx[row] * D_ + d0 + rl * 4);
            sq[row][rl * 4 + 0] = v.x;
            sq[row][rl * 4 + 1] = v.y;
            sq[row][rl * 4 + 2] = v.z;
            sq[row][rl * 4 + 3] = v.w;
        }
        __syncthreads();
#pragma unroll
        for (int dd = 0; dd < 32; dd++) {
            int d = d0 + dd;
            float e = sq[tid][dd];
            float x = X[((size_t)b * D_ + d) * T_ + t];
            out[((size_t)b * D_ + d) * T_ + t] = e;
            float df = e - x;
            loss = fmaf(df, df, loss);
        }
        __syncthreads();
    }

    float* s = &sq[0][0];
    s[tid] = loss;
    __syncthreads();
    for (int off = 128; off > 0; off >>= 1) {
        if (tid < off) s[tid] += s[tid + off];
        __syncthreads();
    }
    if (tid == 0) atomicAdd(&g_loss, (double)s[0]);
}

// ---------------------------------------------------------------------------
// Kernel 4: loss scalar + indices-as-float.
// loss = q_latent + 0.25 * e_latent = 1.25 * mean((q - x)^2)
// ---------------------------------------------------------------------------
__global__ void finalize_kernel(float* __restrict__ out, int out_size) {
    int i = blockIdx.x * blockDim.x + threadIdx.x;
    if (i == 0 && out_size > QSIZE) {
        out[QSIZE] = (float)(g_loss * 1.25 / (double)QSIZE);
    }
    if (i < N_ && out_size >= QSIZE + 1 + N_) {
        out[QSIZE + 1 + i] = (float)g_idx[i];
    }
}

// ---------------------------------------------------------------------------
extern "C" void kernel_launch(void* const* d_in, const int* in_sizes, int n_in,
                              void* d_out, int out_size) {
    const float* X = (const float*)d_in[0];   // [B, D, T] f32
    const float* E = (const float*)d_in[1];   // [K, D]   f32
    float* out = (float*)d_out;

    cudaFuncSetAttribute(argmin_mma_kernel,
                         cudaFuncAttributeMaxDynamicSharedMemorySize, SMTOT);

    e2_kernel<<<K_, 256>>>(E);
    splitE_kernel<<<K_, 256>>>(E);
    x2_kernel<<<dim3(T_ / 256, B_), 256>>>(X);
    argmin_mma_kernel<<<N_ / 128, 256, SMTOT>>>(X);
    gather_kernel<<<dim3(T_ / 256, B_), 256>>>(X, E, out);
    finalize_kernel<<<(N_ + 255) / 256, 256>>>(out, out_size);
}

// round 9
// speedup vs baseline: 2.9789x; 1.1283x over previous
#include <cuda_runtime.h>
#include <cuda_fp16.h>
#include <cstdint>

#define B_ 32
#define D_ 256
#define T_ 2048
#define K_ 1024
#define N_ (B_ * T_)            // 65536 vectors
#define QSIZE (B_ * D_ * T_)    // 16777216 quantized elements

// ---------------- device scratch (no allocation allowed) -------------------
__device__ float  g_e2[K_];
__device__ float  g_x2[N_];
__device__ int    g_idx[N_];
__device__ double g_loss;
// Pre-split codebook (scaled by 2^14): e*2^14 = h + l (residual <= 2^-24 rel)
__device__ __align__(16) __half g_eh[K_ * D_];
__device__ __align__(16) __half g_el[K_ * D_];

#define SCALE_X 16.0f            // 2^4
#define SCALE_E 16384.0f         // 2^14
#define UNSCALE_M2 (-7.62939453125e-6f)   // -2 * 2^-18, exact power of two

// ---------------- smem layout (dynamic) -------------------------------------
// A: [split 0..1][kc 0..3] 16KB tiles of [128 tok][64 d fp16, swizzled rows]
#define SMA   0                 // 131072 bytes
// B double buffer: 2 x 32KB; each: [split 0..1][kc 0..3][32 code][64 d fp16]
#define SMB0  131072
#define SME2  196608            // 1024 floats (full e2 table)
#define SMRV  200704            // 128*2 floats
#define SMRI  201728            // 128*2 ints
#define SMTOT 202752

__device__ __forceinline__ uint32_t smem_u32(const void* p) {
    uint32_t a;
    asm("{ .reg .u64 t; cvta.to.shared.u64 t, %1; cvt.u32.u64 %0, t; }"
        : "=r"(a) : "l"(p));
    return a;
}
__device__ __forceinline__ void ldsm_x4(uint32_t addr, uint32_t* r) {
    asm volatile(
        "ldmatrix.sync.aligned.m8n8.x4.shared.b16 {%0,%1,%2,%3}, [%4];"
        : "=r"(r[0]), "=r"(r[1]), "=r"(r[2]), "=r"(r[3]) : "r"(addr));
}
__device__ __forceinline__ void mma16816(float* c, const uint32_t* a,
                                         const uint32_t* b) {
    asm volatile(
        "mma.sync.aligned.m16n8k16.row.col.f32.f16.f16.f32 "
        "{%0,%1,%2,%3}, {%4,%5,%6,%7}, {%8,%9}, {%0,%1,%2,%3};"
        : "+f"(c[0]), "+f"(c[1]), "+f"(c[2]), "+f"(c[3])
        : "r"(a[0]), "r"(a[1]), "r"(a[2]), "r"(a[3]), "r"(b[0]), "r"(b[1]));
}
__device__ __forceinline__ void cp16(uint32_t dst, const void* src) {
    asm volatile("cp.async.cg.shared.global [%0], [%1], 16;"
                 :: "r"(dst), "l"(src));
}

// ---------------------------------------------------------------------------
// Kernel 1: e2[k] = fl32(sum fl32(E^2)); zero loss accumulator.
// ---------------------------------------------------------------------------
__global__ void e2_kernel(const float* __restrict__ E) {
    int k = blockIdx.x;
    int d = threadIdx.x;
    float v = E[(size_t)k * D_ + d];
    float sq = __fmul_rn(v, v);
    __shared__ double s[256];
    s[d] = (double)sq;
    __syncthreads();
    for (int off = 128; off > 0; off >>= 1) {
        if (d < off) s[d] += s[d + off];
        __syncthreads();
    }
    if (d == 0) g_e2[k] = (float)s[0];
    if (k == 0 && d == 0) g_loss = 0.0;
}

// ---------------------------------------------------------------------------
// Kernel 1b: pre-split codebook into fp16 hi/lo of e*2^14.
// ---------------------------------------------------------------------------
__global__ void splitE_kernel(const float* __restrict__ E) {
    int k = blockIdx.x;
    int d = threadIdx.x;
    size_t o = (size_t)k * D_ + d;
    float es = __fmul_rn(E[o], SCALE_E);        // exact power-of-2 scale
    __half h = __float2half_rn(es);
    __half l = __float2half_rn(__fsub_rn(es, __half2float(h)));
    g_eh[o] = h;
    g_el[o] = l;
}

// ---------------------------------------------------------------------------
// Kernel 1c: x2[n] per vector.
// ---------------------------------------------------------------------------
__global__ __launch_bounds__(256) void x2_kernel(const float* __restrict__ X) {
    int b = blockIdx.y;
    int t = blockIdx.x * 256 + threadIdx.x;
    const float* xp = X + (size_t)b * (D_ * T_) + t;
    double acc = 0.0;
#pragma unroll 8
    for (int d = 0; d < D_; d++) {
        float x = xp[(size_t)d * T_];
        acc += (double)__fmul_rn(x, x);
    }
    g_x2[b * T_ + t] = (float)acc;
}

// ---------------------------------------------------------------------------
// Kernel 2: mma.sync (HMMA) distance GEMM + argmin, cp.async 2-stage B pipe.
// CTA = 128 tokens, 8 warps: wm = wid&3 (32-token group), wn = wid>>2
// (16-code half of the current 32-code tile). 32 code-tiles, double-buffered.
// dot = (AhBh + AhBl + AlBh) with fp16 splits of scaled x,e; fp32 accum.
// Epilogue: dist = fl(fl(x2+e2) - 2*fl(dot)); strict <, tie -> smaller k.
// ---------------------------------------------------------------------------
__global__ __launch_bounds__(256, 1)
void argmin_mma_kernel(const float* __restrict__ X) {
    extern __shared__ char smem[];
    const uint32_t sb = smem_u32(smem);
    const int tid  = threadIdx.x;
    const int lane = tid & 31, wid = tid >> 5;
    const int wm = wid & 3, wn = wid >> 2;
    const int bx = blockIdx.x;
    const int b  = bx >> 4, t0 = (bx & 15) * 128;
    const int n0 = b * T_ + t0;
    const float* Xb = X + (size_t)b * (D_ * T_) + t0;

    // ---- stage A: X tile -> fp16 h/l (scaled by 2^4), swizzled [tok][d] ---
#pragma unroll 4
    for (int i = 0; i < 16; i++) {
        int idx = tid + i * 256;          // 0..4095
        int kc  = idx >> 10;              // 0..3
        int rem = idx & 1023;
        int dp  = rem >> 5;               // d-pair 0..31
        int c4  = rem & 31;               // float4 over tok
        int dg  = kc * 64 + dp * 2;
        float4 va = *(const float4*)(Xb + (size_t)dg * T_ + c4 * 4);
        float4 vb = *(const float4*)(Xb + (size_t)(dg + 1) * T_ + c4 * 4);
        float fa[4] = {va.x, va.y, va.z, va.w};
        float fb[4] = {vb.x, vb.y, vb.z, vb.w};
#pragma unroll
        for (int u = 0; u < 4; u++) {
            int tok = c4 * 4 + u;
            float x0 = __fmul_rn(fa[u], SCALE_X);
            float x1 = __fmul_rn(fb[u], SCALE_X);
            __half h0 = __float2half_rn(x0);
            __half l0 = __float2half_rn(__fsub_rn(x0, __half2float(h0)));
            __half h1 = __float2half_rn(x1);
            __half l1 = __float2half_rn(__fsub_rn(x1, __half2float(h1)));
            uint32_t off = (uint32_t)(tok * 128 + ((dp * 4) ^ ((tok & 7) << 4)));
            *(uint32_t*)(smem + SMA + kc * 16384 + off) =
                (uint32_t)__half_as_ushort(h0) |
                ((uint32_t)__half_as_ushort(h1) << 16);
            *(uint32_t*)(smem + SMA + 65536 + kc * 16384 + off) =
                (uint32_t)__half_as_ushort(l0) |
                ((uint32_t)__half_as_ushort(l1) << 16);
        }
    }
    // stage full e2 table (read only after a later __syncthreads)
    {
        float* se2w = (float*)(smem + SME2);
#pragma unroll
        for (int i = 0; i < 4; i++) se2w[tid + i * 256] = g_e2[tid + i * 256];
    }

    // per-thread owned token rows (4 slots: mb*2 + rowhalf)
    float x2own[4];
#pragma unroll
    for (int slot = 0; slot < 4; slot++) {
        int trow = wm * 32 + (slot >> 1) * 16 + (slot & 1) * 8 + (lane >> 2);
        x2own[slot] = g_x2[n0 + trow];
    }

    float best[4];
    int   bidx[4];
#pragma unroll
    for (int s = 0; s < 4; s++) { best[s] = 3.4e38f; bidx[s] = 0; }

    // lane constants for ldmatrix addressing
    const int g = lane >> 3, r = lane & 7;
    const int tok0  = wm * 32 + (g & 1) * 8 + r;   // A row (mb adds 16)
    const int khA   = g >> 1;
    const uint32_t xrA = (uint32_t)((tok0 & 7) << 4);
    const int code0 = (g >> 1) * 8 + r;            // B row within 16-block
    const int khB   = g & 1;
    const uint32_t xrB = (uint32_t)((code0 & 7) << 4);
    const uint32_t bcol = (uint32_t)((wn * 16 + code0) * 128);

    // ---- B-tile prefetch (32 codes = 32KB: 2 splits x 4 kc x 32 rows) -----
    auto prefetch = [&](int ct) {
        int cbase = ct * 32;
        uint32_t bufo = sb + SMB0 + (uint32_t)(ct & 1) * 32768;
#pragma unroll
        for (int i = 0; i < 8; i++) {
            int idx = tid + i * 256;       // 0..2047
            int s   = idx >> 10;
            int rem = idx & 1023;
            int kc  = rem >> 8;
            int r2  = rem & 255;
            int row = r2 >> 3, c16 = r2 & 7;
            const __half* src = (s ? g_el : g_eh)
                + (size_t)(cbase + row) * D_ + kc * 64 + c16 * 8;
            uint32_t dst = bufo + s * 16384 + kc * 4096 + row * 128
                         + (uint32_t)((c16 * 16) ^ ((row & 7) << 4));
            cp16(dst, src);
        }
        asm volatile("cp.async.commit_group;" ::: "memory");
    };

    prefetch(0);

    const float* se2 = (const float*)(smem + SME2);

    for (int ct = 0; ct < 32; ct++) {
        __syncthreads();                       // all done reading buf (ct+1)&1
        if (ct + 1 < 32) {
            prefetch(ct + 1);
            asm volatile("cp.async.wait_group 1;" ::: "memory");
        } else {
            asm volatile("cp.async.wait_group 0;" ::: "memory");
        }
        __syncthreads();                       // tile ct visible block-wide

        // ---- mainloop: 32 codes x K=256 (16 k16 steps) -------------------
        float acc[2][2][4];
#pragma unroll
        for (int mb = 0; mb < 2; mb++)
#pragma unroll
            for (int nb = 0; nb < 2; nb++)
#pragma unroll
                for (int e = 0; e < 4; e++) acc[mb][nb][e] = 0.f;

        uint32_t bufo = sb + SMB0 + (uint32_t)(ct & 1) * 32768;
#pragma unroll
        for (int kc = 0; kc < 4; kc++) {
            uint32_t abase = sb + SMA + kc * 16384 + tok0 * 128;
            uint32_t bbase = bufo + kc * 4096 + bcol;
#pragma unroll
            for (int ks = 0; ks < 4; ks++) {
                uint32_t da = (uint32_t)((ks * 32 + khA * 16) ^ xrA);
                uint32_t db = (uint32_t)((ks * 32 + khB * 16) ^ xrB);
                uint32_t Ah[2][4], Al[2][4], Bh[4], Bl[4];
#pragma unroll
                for (int mb = 0; mb < 2; mb++) {
                    ldsm_x4(abase + mb * 2048 + da, Ah[mb]);
                    ldsm_x4(abase + 65536 + mb * 2048 + da, Al[mb]);
                }
                ldsm_x4(bbase + db, Bh);
                ldsm_x4(bbase + 16384 + db, Bl);
#pragma unroll
                for (int mb = 0; mb < 2; mb++)
#pragma unroll
                    for (int nb = 0; nb < 2; nb++) {
                        const uint32_t* bh = &Bh[2 * nb];
                        const uint32_t* bl = &Bl[2 * nb];
                        mma16816(acc[mb][nb], Ah[mb], bh);
                        mma16816(acc[mb][nb], Ah[mb], bl);
                        mma16816(acc[mb][nb], Al[mb], bh);
                    }
            }
        }

        // ---- epilogue: exact ref rounding + running argmin ---------------
        int cbase = ct * 32;
#pragma unroll
        for (int mb = 0; mb < 2; mb++)
#pragma unroll
            for (int nb = 0; nb < 2; nb++)
#pragma unroll
                for (int e = 0; e < 4; e++) {
                    int slot = mb * 2 + (e >> 1);
                    int k    = cbase + wn * 16 + nb * 8
                             + 2 * (lane & 3) + (e & 1);
                    float C    = __fadd_rn(x2own[slot], se2[k]);
                    float m2g  = __fmul_rn(acc[mb][nb][e], UNSCALE_M2); // exact
                    float dist = __fadd_rn(C, m2g);
                    if (dist < best[slot]) { best[slot] = dist; bidx[slot] = k; }
                }
    }

    // ---- reduce: 4 lanes per row (shfl), then 2 wn warps (smem) ----------
    float* rv = (float*)(smem + SMRV);
    int*   ri = (int*)(smem + SMRI);
    __syncthreads();
#pragma unroll
    for (int slot = 0; slot < 4; slot++) {
        float v = best[slot];
        int   ix = bidx[slot];
#pragma unroll
        for (int off = 1; off < 4; off <<= 1) {
            float ov = __shfl_xor_sync(0xffffffffu, v, off);
            int   oi = __shfl_xor_sync(0xffffffffu, ix, off);
            if (ov < v || (ov == v && oi < ix)) { v = ov; ix = oi; }
        }
        if ((lane & 3) == 0) {
            int trow = wm * 32 + (slot >> 1) * 16 + (slot & 1) * 8 + (lane >> 2);
            rv[trow * 2 + wn] = v;
            ri[trow * 2 + wn] = ix;
        }
    }
    __syncthreads();
    if (tid < 128) {
        float v0 = rv[tid * 2], v1 = rv[tid * 2 + 1];
        int   i0 = ri[tid * 2], i1 = ri[tid * 2 + 1];
        int sel = (v1 < v0 || (v1 == v0 && i1 < i0)) ? i1 : i0;
        g_idx[n0 + tid] = sel;
    }
}

// ---------------------------------------------------------------------------
// Kernel 3: gather codebook rows -> quantized output, fused loss.
// ---------------------------------------------------------------------------
__global__ __launch_bounds__(256) void gather_kernel(
    const float* __restrict__ X, const float* __restrict__ E,
    float* __restrict__ out)
{
    __shared__ float sq[256][33];
    __shared__ int   sidx[256];

    const int b   = blockIdx.y;
    const int t0  = blockIdx.x * 256;
    const int tid = threadIdx.x;
    const int t   = t0 + tid;

    sidx[tid] = g_idx[b * T_ + t];
    __syncthreads();

    const int rg = tid >> 3;
    const int rl = tid & 7;

    float loss = 0.f;
    for (int d0 = 0; d0 < D_; d0 += 32) {
#pragma unroll
        for (int r0 = 0; r0 < 256; r0 += 32) {
            int row = r0 + rg;
            float4 v = *reinterpret_cast<const float4*>(
                E + (size_t)sidx[row] * D_ + d0 + rl * 4);
            sq[row][rl * 4 + 0] = v.x;
            sq[row][rl * 4 + 1] = v.y;
            sq[row][rl * 4 + 2] = v.z;
            sq[row][rl * 4 + 3] = v.w;
        }
        __syncthreads();
#pragma unroll
        for (int dd = 0; dd < 32; dd++) {
            int d = d0 + dd;
            float e = sq[tid][dd];
            float x = X[((size_t)b * D_ + d) * T_ + t];
            out[((size_t)b * D_ + d) * T_ + t] = e;
            float df = e - x;
            loss = fmaf(df, df, loss);
        }
        __syncthreads();
    }

    float* s = &sq[0][0];
    s[tid] = loss;
    __syncthreads();
    for (int off = 128; off > 0; off >>= 1) {
        if (tid < off) s[tid] += s[tid + off];
        __syncthreads();
    }
    if (tid == 0) atomicAdd(&g_loss, (double)s[0]);
}

// ---------------------------------------------------------------------------
// Kernel 4: loss scalar + indices-as-float.
// loss = q_latent + 0.25 * e_latent = 1.25 * mean((q - x)^2)
// ---------------------------------------------------------------------------
__global__ void finalize_kernel(float* __restrict__ out, int out_size) {
    int i = blockIdx.x * blockDim.x + threadIdx.x;
    if (i == 0 && out_size > QSIZE) {
        out[QSIZE] = (float)(g_loss * 1.25 / (double)QSIZE);
    }
    if (i < N_ && out_size >= QSIZE + 1 + N_) {
        out[QSIZE + 1 + i] = (float)g_idx[i];
    }
}

// ---------------------------------------------------------------------------
extern "C" void kernel_launch(void* const* d_in, const int* in_sizes, int n_in,
                              void* d_out, int out_size) {
    const float* X = (const float*)d_in[0];   // [B, D, T] f32
    const float* E = (const float*)d_in[1];   // [K, D]   f32
    float* out = (float*)d_out;

    cudaFuncSetAttribute(argmin_mma_kernel,
                         cudaFuncAttributeMaxDynamicSharedMemorySize, SMTOT);

    e2_kernel<<<K_, 256>>>(E);
    splitE_kernel<<<K_, 256>>>(E);
    x2_kernel<<<dim3(T_ / 256, B_), 256>>>(X);
    argmin_mma_kernel<<<N_ / 128, 256, SMTOT>>>(X);
    gather_kernel<<<dim3(T_ / 256, B_), 256>>>(X, E, out);
    finalize_kernel<<<(N_ + 255) / 256, 256>>>(out, out_size);
}